// round 1
// baseline (speedup 1.0000x reference)
#include <cuda_runtime.h>
#include <math.h>

#define NCH   256
#define OUTSZ 7
#define GPTS  14          // OUT * SR
#define CHUNK 32          // channels per block (grid.y = 256/32 = 8)
#define NWARP 8

__global__ __launch_bounds__(256, 8)
void msroi_kernel(const float* __restrict__ f0,
                  const float* __restrict__ f1,
                  const float* __restrict__ f2,
                  const float* __restrict__ f3,
                  const float* __restrict__ boxes,
                  float* __restrict__ out,
                  int nroi)
{
    const int roi = blockIdx.x;
    const int tid = threadIdx.x;

    __shared__ int   sx0[GPTS], sx1[GPTS], sy0[GPTS], sy1[GPTS];
    __shared__ float swx0[GPTS], swx1[GPTS], swy0[GPTS], swy1[GPTS];
    __shared__ const float* sbase;     // feature base for (level, batch)
    __shared__ int sW;
    __shared__ int sHW;

    // ---- per-ROI params (computed redundantly; cheap) ----
    const float bx1 = boxes[roi * 4 + 0];
    const float by1 = boxes[roi * 4 + 1];
    const float bx2 = boxes[roi * 4 + 2];
    const float by2 = boxes[roi * 4 + 3];

    // FPN level heuristic (fp32, matching reference)
    float area = (bx2 - bx1) * (by2 - by1);
    float s    = sqrtf(fmaxf(area, 0.0f));
    float lvlf = floorf(4.0f + log2f(s / 224.0f) + 1e-6f);
    lvlf = fminf(fmaxf(lvlf, 2.0f), 5.0f);
    const int lvl = (int)lvlf - 2;                 // 0..3

    const int   Hs[4] = {200, 100, 50, 25};
    const float scs[4] = {0.25f, 0.125f, 0.0625f, 0.03125f};
    const int   H = Hs[lvl];
    const int   W = H;                             // square maps
    const float scale = scs[lvl];

    // ---- sample-coordinate tables (threads 0..27) ----
    if (tid < 2 * GPTS) {
        const bool isY = (tid >= GPTS);
        const int  g   = isY ? (tid - GPTS) : tid;
        const float c1 = (isY ? by1 : bx1) * scale;
        const float c2 = (isY ? by2 : bx2) * scale;
        const float rsz = fmaxf(c2 - c1, 1.0f);
        const float bin = rsz / (float)OUTSZ;
        // coord = start + (g/2)*bin + ((g%2)+0.5) * bin / 2   (match ref op order)
        const float coord = c1 + (float)(g >> 1) * bin
                               + ((float)(g & 1) + 0.5f) * bin / 2.0f;
        const int   D = isY ? H : W;
        const bool  valid = (coord >= -1.0f) && (coord <= (float)D);
        const float cc = fminf(fmaxf(coord, 0.0f), (float)(D - 1));
        int   i0 = (int)floorf(cc);
        int   i1 = min(i0 + 1, D - 1);
        float l  = cc - (float)i0;
        float h  = 1.0f - l;
        if (!valid) { l = 0.0f; h = 0.0f; }
        if (isY) { sy0[g] = i0; sy1[g] = i1; swy0[g] = h; swy1[g] = l; }
        else     { sx0[g] = i0; sx1[g] = i1; swx0[g] = h; swx1[g] = l; }
    }
    if (tid == 0) {
        const int perB = nroi >> 1;                // B = 2
        const int b = roi / perB;
        const float* fl = (lvl == 0) ? f0 : (lvl == 1) ? f1 : (lvl == 2) ? f2 : f3;
        sHW = H * W;
        sW  = W;
        sbase = fl + (size_t)b * (size_t)NCH * (size_t)(H * W);
    }
    __syncthreads();

    const int warp = tid >> 5;
    const int lane = tid & 31;

    // lane -> (gx, x-tap); lanes 28..31 idle (zero weight)
    float xw = 0.0f;
    int   xc = 0;
    if (lane < 28) {
        const int gx = lane >> 1;
        const int xt = lane & 1;
        xc = xt ? sx1[gx] : sx0[gx];
        xw = xt ? swx1[gx] : swx0[gx];
    }

    const float* base = sbase;
    const int Wd  = sW;
    const int HWd = sHW;
    const int cbase = blockIdx.y * CHUNK;
    const size_t out_roi = (size_t)roi * NCH * (OUTSZ * OUTSZ);

    // tasks: (channel in chunk, bin-row by)  -> CHUNK*7 = 224 tasks over 8 warps
    for (int t = warp; t < CHUNK * OUTSZ; t += NWARP) {
        const int c  = cbase + t / OUTSZ;
        const int by = t % OUTSZ;
        const float* fc = base + (size_t)c * HWd;

        float acc = 0.0f;
        #pragma unroll
        for (int gys = 0; gys < 2; ++gys) {
            const int gy  = 2 * by + gys;
            const int y0  = sy0[gy];
            const int y1  = sy1[gy];
            const float w0 = swy0[gy] * xw;
            const float w1 = swy1[gy] * xw;
            const float* row0 = fc + (size_t)y0 * Wd;
            const float* row1 = fc + (size_t)y1 * Wd;
            if (w0 != 0.0f) acc = fmaf(w0, __ldg(row0 + xc), acc);
            if (w1 != 0.0f) acc = fmaf(w1, __ldg(row1 + xc), acc);
        }

        // reduce groups of 4 lanes: (gx even/odd) x (x-tap 0/1) -> one bin bx
        acc += __shfl_down_sync(0xffffffffu, acc, 1);
        acc += __shfl_down_sync(0xffffffffu, acc, 2);

        if ((lane & 3) == 0 && lane < 28) {
            const int bxo = lane >> 2;             // 0..6
            out[out_roi + (size_t)c * (OUTSZ * OUTSZ) + by * OUTSZ + bxo] = acc * 0.25f;
        }
    }
}

extern "C" void kernel_launch(void* const* d_in, const int* in_sizes, int n_in,
                              void* d_out, int out_size)
{
    const float* f0 = (const float*)d_in[0];
    const float* f1 = (const float*)d_in[1];
    const float* f2 = (const float*)d_in[2];
    const float* f3 = (const float*)d_in[3];
    const float* bx = (const float*)d_in[4];
    float* out = (float*)d_out;

    const int nroi = in_sizes[4] / 4;              // 512
    dim3 grid(nroi, NCH / CHUNK, 1);               // 512 x 8
    msroi_kernel<<<grid, 256>>>(f0, f1, f2, f3, bx, out, nroi);
}

// round 2
// speedup vs baseline: 1.2740x; 1.2740x over previous
#include <cuda_runtime.h>
#include <math.h>

#define NCH   256
#define OUTSZ 7
#define GPTS  14          // OUT * SR
#define GRIDY 2           // channel splits
#define CPB   (NCH / GRIDY)       // channels per block = 128
#define PPW   (CPB / 2 / 8)       // channel-pairs per warp = 8

__global__ __launch_bounds__(256, 8)
void msroi_kernel(const float* __restrict__ f0,
                  const float* __restrict__ f1,
                  const float* __restrict__ f2,
                  const float* __restrict__ f3,
                  const float* __restrict__ boxes,
                  float* __restrict__ out,
                  int nroi)
{
    const int roi = blockIdx.x;
    const int tid = threadIdx.x;

    __shared__ int   sx0[16], sx1[16];
    __shared__ float swx0[16], swx1[16];
    __shared__ int   sry0[GPTS], sry1[GPTS];        // y row offsets (elements)
    __shared__ float swy0[GPTS], swy1[GPTS];
    __shared__ const float* sbase;
    __shared__ int sHW;

    // ---- per-ROI params (computed redundantly by all threads; cheap) ----
    const float bx1 = boxes[roi * 4 + 0];
    const float by1 = boxes[roi * 4 + 1];
    const float bx2 = boxes[roi * 4 + 2];
    const float by2 = boxes[roi * 4 + 3];

    float area = (bx2 - bx1) * (by2 - by1);
    float s    = sqrtf(fmaxf(area, 0.0f));
    float lvlf = floorf(4.0f + log2f(s / 224.0f) + 1e-6f);
    lvlf = fminf(fmaxf(lvlf, 2.0f), 5.0f);
    const int lvl = (int)lvlf - 2;                 // 0..3

    const int   Hs[4]  = {200, 100, 50, 25};
    const float scs[4] = {0.25f, 0.125f, 0.0625f, 0.03125f};
    const int   H = Hs[lvl];
    const int   W = H;
    const float scale = scs[lvl];

    // ---- x tables: threads 0..15 (gx 14,15 are zero-weight pads) ----
    if (tid < 16) {
        const int g = tid;
        int   i0 = 0, i1 = 0;
        float h = 0.0f, l = 0.0f;
        if (g < GPTS) {
            const float c1 = bx1 * scale;
            const float c2 = bx2 * scale;
            const float bin = fmaxf(c2 - c1, 1.0f) / (float)OUTSZ;
            const float coord = c1 + (float)(g >> 1) * bin
                                   + ((float)(g & 1) + 0.5f) * bin / 2.0f;
            const bool valid = (coord >= -1.0f) && (coord <= (float)W);
            const float cc = fminf(fmaxf(coord, 0.0f), (float)(W - 1));
            i0 = (int)floorf(cc);
            i1 = min(i0 + 1, W - 1);
            l  = valid ? (cc - (float)i0) * 0.5f : 0.0f;   // fold 1/2 of the 1/4 avg
            h  = valid ? 0.5f - l : 0.0f;
        }
        sx0[g] = i0;  sx1[g] = i1;
        swx0[g] = h;  swx1[g] = l;
    } else if (tid < 16 + GPTS) {
        // ---- y tables: threads 16..29 ----
        const int g = tid - 16;
        const float c1 = by1 * scale;
        const float c2 = by2 * scale;
        const float bin = fmaxf(c2 - c1, 1.0f) / (float)OUTSZ;
        const float coord = c1 + (float)(g >> 1) * bin
                               + ((float)(g & 1) + 0.5f) * bin / 2.0f;
        const bool valid = (coord >= -1.0f) && (coord <= (float)H);
        const float cc = fminf(fmaxf(coord, 0.0f), (float)(H - 1));
        int   i0 = (int)floorf(cc);
        int   i1 = min(i0 + 1, H - 1);
        float l  = valid ? (cc - (float)i0) * 0.5f : 0.0f;  // other 1/2 of the avg
        float h  = valid ? 0.5f - l : 0.0f;
        sry0[g] = i0 * W;  sry1[g] = i1 * W;
        swy0[g] = h;       swy1[g] = l;
    } else if (tid == 30) {
        const int perB = nroi >> 1;                // B = 2
        const int b = roi / perB;
        const float* fl = (lvl == 0) ? f0 : (lvl == 1) ? f1 : (lvl == 2) ? f2 : f3;
        sHW = H * W;
        sbase = fl + (size_t)b * (size_t)NCH * (size_t)(H * W);
    }
    __syncthreads();

    const int warp = tid >> 5;
    const int lane = tid & 31;
    const int half = lane >> 4;                    // 0/1 -> channel within pair
    const int gx   = lane & 15;                    // 0..15 (14,15 zero weight)

    const int   x0  = sx0[gx];
    const int   x1  = sx1[gx];
    const float wx0 = swx0[gx];
    const float wx1 = swx1[gx];

    const float* base = sbase;
    const int HW  = sHW;
    const int c0  = blockIdx.y * CPB + warp * (2 * PPW) + half;   // first channel
    const bool writer = ((gx & 1) == 0) && (gx < GPTS);
    const size_t out_roi = (size_t)roi * NCH * (OUTSZ * OUTSZ);

    const float* q0base = base + (size_t)c0 * HW + x0;
    const float* q1base = base + (size_t)c0 * HW + x1;

    for (int by = 0; by < OUTSZ; ++by) {
        const int   ra0 = sry0[2 * by],     ra1 = sry1[2 * by];
        const int   rb0 = sry0[2 * by + 1], rb1 = sry1[2 * by + 1];
        const float wa0 = swy0[2 * by],     wa1 = swy1[2 * by];
        const float wb0 = swy0[2 * by + 1], wb1 = swy1[2 * by + 1];

        const float* q0 = q0base;
        const float* q1 = q1base;
        float* o = out + out_roi + (size_t)c0 * (OUTSZ * OUTSZ)
                       + by * OUTSZ + (gx >> 1);

        #pragma unroll
        for (int i = 0; i < PPW; ++i) {
            const float va0 = __ldg(q0 + ra0);
            const float va1 = __ldg(q1 + ra0);
            const float vb0 = __ldg(q0 + ra1);
            const float vb1 = __ldg(q1 + ra1);
            const float vc0 = __ldg(q0 + rb0);
            const float vc1 = __ldg(q1 + rb0);
            const float vd0 = __ldg(q0 + rb1);
            const float vd1 = __ldg(q1 + rb1);

            float s0 = wa0 * va0;
            s0 = fmaf(wa1, vb0, s0);
            s0 = fmaf(wb0, vc0, s0);
            s0 = fmaf(wb1, vd0, s0);
            float s1 = wa0 * va1;
            s1 = fmaf(wa1, vb1, s1);
            s1 = fmaf(wb0, vc1, s1);
            s1 = fmaf(wb1, vd1, s1);

            float acc = fmaf(wx1, s1, wx0 * s0);
            acc += __shfl_down_sync(0xffffffffu, acc, 1);

            if (writer) *o = acc;

            q0 += 2 * HW;
            q1 += 2 * HW;
            o  += 2 * (OUTSZ * OUTSZ);
        }
    }
}

extern "C" void kernel_launch(void* const* d_in, const int* in_sizes, int n_in,
                              void* d_out, int out_size)
{
    const float* f0 = (const float*)d_in[0];
    const float* f1 = (const float*)d_in[1];
    const float* f2 = (const float*)d_in[2];
    const float* f3 = (const float*)d_in[3];
    const float* bx = (const float*)d_in[4];
    float* out = (float*)d_out;

    const int nroi = in_sizes[4] / 4;              // 512
    dim3 grid(nroi, GRIDY, 1);                     // 512 x 2
    msroi_kernel<<<grid, 256>>>(f0, f1, f2, f3, bx, out, nroi);
}

// round 3
// speedup vs baseline: 2.3169x; 1.8186x over previous
#include <cuda_runtime.h>
#include <math.h>

#define NCH   256
#define OUTSZ 7
#define GPTS  14                 // OUT * SR
#define GRIDY 4                  // channel splits
#define CPB   (NCH / GRIDY)      // 64 channels per block
#define NWARP 8
#define CPW   (CPB / NWARP)      // 8 channels per warp

__global__ __launch_bounds__(256, 6)
void msroi_kernel(const float* __restrict__ f0,
                  const float* __restrict__ f1,
                  const float* __restrict__ f2,
                  const float* __restrict__ f3,
                  const float* __restrict__ boxes,
                  float* __restrict__ out,
                  int nroi)
{
    const int roi = blockIdx.x;
    const int tid = threadIdx.x;

    // per-lane tap tables: 28 taps = 14 grid points x 2 bilinear taps
    __shared__ int   sxc[32];     // x column index per tap
    __shared__ float swx[32];     // x weight per tap (x 0.25 avg fold)
    __shared__ int   sry[28];     // y row offset (elements) per tap
    __shared__ float swy[28];     // y weight per tap
    __shared__ const float* sbase;
    __shared__ int sHW;

    // ---- per-ROI params (computed redundantly by all threads; cheap) ----
    const float bx1 = boxes[roi * 4 + 0];
    const float by1 = boxes[roi * 4 + 1];
    const float bx2 = boxes[roi * 4 + 2];
    const float by2 = boxes[roi * 4 + 3];

    float area = (bx2 - bx1) * (by2 - by1);
    float s    = sqrtf(fmaxf(area, 0.0f));
    float lvlf = floorf(4.0f + log2f(s / 224.0f) + 1e-6f);
    lvlf = fminf(fmaxf(lvlf, 2.0f), 5.0f);
    const int lvl = (int)lvlf - 2;                 // 0..3

    const int   Hs[4]  = {200, 100, 50, 25};
    const float scs[4] = {0.25f, 0.125f, 0.0625f, 0.03125f};
    const int   H = Hs[lvl];
    const int   W = H;
    const float scale = scs[lvl];

    if (tid < 32) {
        // ---- x tap tables (taps 28..31 zero-weight) ----
        const int g = tid;
        int   xc = 0;
        float w  = 0.0f;
        if (g < 28) {
            const int gx = g >> 1;
            const int xt = g & 1;
            const float c1 = bx1 * scale;
            const float c2 = bx2 * scale;
            const float bin = fmaxf(c2 - c1, 1.0f) / (float)OUTSZ;
            const float coord = c1 + (float)(gx >> 1) * bin
                                   + ((float)(gx & 1) + 0.5f) * bin / 2.0f;
            const bool valid = (coord >= -1.0f) && (coord <= (float)W);
            const float cc = fminf(fmaxf(coord, 0.0f), (float)(W - 1));
            const int i0 = (int)floorf(cc);
            const int i1 = min(i0 + 1, W - 1);
            const float l = cc - (float)i0;
            const float h = 1.0f - l;
            xc = xt ? i1 : i0;
            w  = valid ? (xt ? l : h) * 0.25f : 0.0f;   // fold the 1/4 bin average
        }
        sxc[g] = xc;
        swx[g] = w;
    } else if (tid < 64) {
        // ---- y tap tables ----
        const int g = tid - 32;
        if (g < 28) {
            const int gy = g >> 1;
            const int yt = g & 1;
            const float c1 = by1 * scale;
            const float c2 = by2 * scale;
            const float bin = fmaxf(c2 - c1, 1.0f) / (float)OUTSZ;
            const float coord = c1 + (float)(gy >> 1) * bin
                                   + ((float)(gy & 1) + 0.5f) * bin / 2.0f;
            const bool valid = (coord >= -1.0f) && (coord <= (float)H);
            const float cc = fminf(fmaxf(coord, 0.0f), (float)(H - 1));
            const int i0 = (int)floorf(cc);
            const int i1 = min(i0 + 1, H - 1);
            const float l = cc - (float)i0;
            const float h = 1.0f - l;
            sry[g] = (yt ? i1 : i0) * W;
            swy[g] = valid ? (yt ? l : h) : 0.0f;
        } else if (g == 28) {
            const int perB = nroi >> 1;            // B = 2
            const int b = roi / perB;
            const float* fl = (lvl == 0) ? f0 : (lvl == 1) ? f1
                            : (lvl == 2) ? f2 : f3;
            sHW = H * W;
            sbase = fl + (size_t)b * (size_t)NCH * (size_t)(H * W);
        }
    }
    __syncthreads();

    const int warp = tid >> 5;
    const int lane = tid & 31;

    const int   xc = sxc[lane];
    const float wx = swx[lane];
    const bool  act    = lane < 28;
    const bool  writer = act && ((lane & 3) == 0);

    const int HW = sHW;
    const int c0 = blockIdx.y * CPB + warp * CPW;
    const float* q = sbase + (size_t)c0 * HW + xc;
    float* o = out + (size_t)roi * (NCH * OUTSZ * OUTSZ)
                   + (size_t)c0 * (OUTSZ * OUTSZ) + (lane >> 2);

    #pragma unroll 1
    for (int i = 0; i < CPW; ++i) {
        #pragma unroll
        for (int by = 0; by < OUTSZ; ++by) {
            const int   r0 = sry[4 * by + 0];
            const int   r1 = sry[4 * by + 1];
            const int   r2 = sry[4 * by + 2];
            const int   r3 = sry[4 * by + 3];
            const float w0 = swy[4 * by + 0];
            const float w1 = swy[4 * by + 1];
            const float w2 = swy[4 * by + 2];
            const float w3 = swy[4 * by + 3];

            float v0 = 0.0f, v1 = 0.0f, v2 = 0.0f, v3 = 0.0f;
            if (act) {
                v0 = __ldg(q + r0);
                v1 = __ldg(q + r1);
                v2 = __ldg(q + r2);
                v3 = __ldg(q + r3);
            }
            float a = w0 * v0;
            a = fmaf(w1, v1, a);
            a = fmaf(w2, v2, a);
            a = fmaf(w3, v3, a);
            a *= wx;

            a += __shfl_down_sync(0xffffffffu, a, 1);
            a += __shfl_down_sync(0xffffffffu, a, 2);

            if (writer) __stcs(o + by * OUTSZ, a);
        }
        q += HW;
        o += OUTSZ * OUTSZ;
    }
}

extern "C" void kernel_launch(void* const* d_in, const int* in_sizes, int n_in,
                              void* d_out, int out_size)
{
    const float* f0 = (const float*)d_in[0];
    const float* f1 = (const float*)d_in[1];
    const float* f2 = (const float*)d_in[2];
    const float* f3 = (const float*)d_in[3];
    const float* bx = (const float*)d_in[4];
    float* out = (float*)d_out;

    const int nroi = in_sizes[4] / 4;              // 512
    dim3 grid(nroi, GRIDY, 1);                     // 512 x 4
    msroi_kernel<<<grid, 256>>>(f0, f1, f2, f3, bx, out, nroi);
}